// round 8
// baseline (speedup 1.0000x reference)
#include <cuda_runtime.h>
#include <stdint.h>

#define IMH 1024
#define IMW 1024
#define NB  8
#define WPR 32   // 32-bit words per image row

// Bit-packed strong/weak planes (static device scratch, no allocs)
__device__ uint32_t g_strong[NB * IMH * WPR];
__device__ uint32_t g_weak[NB * IMH * WPR];

#define ROWS1 32   // output rows per canny_front block

// ---------------------------------------------------------------------------
// K1: rolling pipeline, 512 threads x 2 cols, full 1024-wide rows.
// Register windows (3 rows x 4 cols) carry vertical taps for raw/bl/mag;
// smem (depth-2 parity rings, rows of 1028 floats: data at idx 2..1025,
// zero guards at idx 1 and 1026) provides only each thread's +-1 horizontal
// neighbor scalars -> 6 LDS + 3 STS.64 per thread-iteration (was ~36 ops).
// All FP decision expressions are verbatim from the round-4 passing kernel.
// Pipeline at iter i (r = y0-3+i): store raw(r), bl(r-2), mag(r-4); sync;
// assemble windows; compute bl(r-1), mag+bin(r-3); NMS+pack row r-5.
// Hazard: slot p is re-stored in iter i+2, after iter i+1's sync, which is
// after all iter-i reads of p -> safe with one sync per iteration.
// ---------------------------------------------------------------------------
__global__ void __launch_bounds__(512) canny_front(const float* __restrict__ in)
{
    __shared__ __align__(16) float s_raw[2][1028];
    __shared__ __align__(16) float s_bl [2][1028];
    __shared__ __align__(16) float s_mag[2][1028];

    const int t  = threadIdx.x;          // 0..511
    const int b  = blockIdx.y;
    const int y0 = blockIdx.x * ROWS1;
    const float* img = in + (size_t)b * IMH * IMW;
    const int cx = 2 * t;                // owned columns cx, cx+1

    // zero guards (col -1 -> idx 1, col 1024 -> idx 1026), both parities
    if (t < 2) {
        int g = 1 + t * 1025;
        s_raw[0][g] = 0.f; s_raw[1][g] = 0.f;
        s_bl [0][g] = 0.f; s_bl [1][g] = 0.f;
        s_mag[0][g] = 0.f; s_mag[1][g] = 0.f;
    }

    // register windows: cols cx-1 .. cx+2
    float rw0[4], rw1[4], rw2[4];        // raw rows r-2, r-1, r
    float bw0[4], bw1[4], bw2[4];        // bl  rows r-4, r-3, r-2
    float mw0[4], mw1[4], mw2[4];        // mag rows r-6, r-5, r-4
    #pragma unroll
    for (int k = 0; k < 4; k++) {
        rw0[k]=rw1[k]=rw2[k]=0.f; bw0[k]=bw1[k]=bw2[k]=0.f; mw0[k]=mw1[k]=mw2[k]=0.f;
    }
    float2 blp  = make_float2(0.f, 0.f);   // bl(r-2) pending store
    float2 magp = make_float2(0.f, 0.f);   // mag(r-4) pending store
    int binm1[2] = {0,0}, binm2[2] = {0,0};

    const int r_start = y0 - 3;

    float2 rv = make_float2(0.f, 0.f);
    if ((unsigned)r_start < IMH)
        rv = ((const float2*)(img + (size_t)r_start * IMW))[t];

    #pragma unroll 2
    for (int i = 0; i < ROWS1 + 8; ++i) {
        const int r = r_start + i;
        const int p = i & 1;

        // ---- store phase (vectorized, aligned: base+2 floats = 8B) ----
        ((float2*)(s_raw[p] + 2))[t] = rv;
        ((float2*)(s_bl [p] + 2))[t] = blp;
        ((float2*)(s_mag[p] + 2))[t] = magp;
        __syncthreads();

        // prefetch raw(r+1)
        float2 rvn = make_float2(0.f, 0.f);
        if ((unsigned)(r + 1) < IMH)
            rvn = ((const float2*)(img + (size_t)(r + 1) * IMW))[t];

        // ---- window shifts + assemble new bottom rows (neighbors via smem) ----
        #pragma unroll
        for (int k = 0; k < 4; k++) { rw0[k]=rw1[k]; rw1[k]=rw2[k]; }
        rw2[0] = s_raw[p][1 + cx];
        rw2[1] = rv.x; rw2[2] = rv.y;
        rw2[3] = s_raw[p][4 + cx];

        #pragma unroll
        for (int k = 0; k < 4; k++) { bw0[k]=bw1[k]; bw1[k]=bw2[k]; }
        bw2[0] = s_bl[p][1 + cx];
        bw2[1] = blp.x; bw2[2] = blp.y;
        bw2[3] = s_bl[p][4 + cx];

        #pragma unroll
        for (int k = 0; k < 4; k++) { mw0[k]=mw1[k]; mw1[k]=mw2[k]; }
        mw2[0] = s_mag[p][1 + cx];
        mw2[1] = magp.x; mw2[2] = magp.y;
        mw2[3] = s_mag[p][4 + cx];

        // ---- blur(r-1): direct 9-tap, verbatim expression ----
        float2 bln = make_float2(0.f, 0.f);
        if (r >= y0 - 1 && (unsigned)(r - 1) < IMH) {
            bln.x = 0.0625f * rw0[0] + 0.125f * rw0[1] + 0.0625f * rw0[2]
                  + 0.125f  * rw1[0] + 0.25f  * rw1[1] + 0.125f  * rw1[2]
                  + 0.0625f * rw2[0] + 0.125f * rw2[1] + 0.0625f * rw2[2];
            bln.y = 0.0625f * rw0[1] + 0.125f * rw0[2] + 0.0625f * rw0[3]
                  + 0.125f  * rw1[1] + 0.25f  * rw1[2] + 0.125f  * rw1[3]
                  + 0.0625f * rw2[1] + 0.125f * rw2[2] + 0.0625f * rw2[3];
        }

        // ---- sobel + mag + bin at row r-3: verbatim expressions ----
        float magn[2] = {0.f, 0.f};
        int   binn[2] = {0, 0};
        if (r >= y0 + 2 && (unsigned)(r - 3) < IMH) {
            #pragma unroll
            for (int j = 0; j < 2; j++) {
                float gx = (bw0[j+2] - bw0[j]) + 2.0f * (bw1[j+2] - bw1[j]) + (bw2[j+2] - bw2[j]);
                float gy = (bw2[j] - bw0[j]) + 2.0f * (bw2[j+1] - bw0[j+1]) + (bw2[j+2] - bw0[j+2]);
                magn[j] = sqrtf(gx * gx + gy * gy);
                float ax = fabsf(gx), ay = fabsf(gy);
                bool ss = ((__float_as_uint(gx) ^ __float_as_uint(gy)) >> 31) == 0u;
                binn[j] = (ay < 0.41421356237309503f * ax) ? 0 :
                          (ay >= 2.414213562373095f  * ax) ? 2 : (ss ? 1 : 3);
            }
        }

        // ---- NMS + double threshold + bitpack at row r-5 ----
        if (i >= 8) {
            bool s0, w0, s1, w1;
            {
                float m = mw1[1];
                int bin = binm2[0];
                int dc = (bin <= 1) ? 1 : ((bin == 2) ? 0 : -1);
                const float* p1 = (bin == 0) ? mw1 : mw0;
                const float* p2 = (bin == 0) ? mw1 : mw2;
                float n1 = p1[1 + dc], n2 = p2[1 - dc];
                float sup = (m >= n1 && m >= n2) ? m : 0.f;
                s0 = sup >= 0.3f;
                w0 = (sup >= 0.1f) && (sup < 0.3f);
            }
            {
                float m = mw1[2];
                int bin = binm2[1];
                int dc = (bin <= 1) ? 1 : ((bin == 2) ? 0 : -1);
                const float* p1 = (bin == 0) ? mw1 : mw0;
                const float* p2 = (bin == 0) ? mw1 : mw2;
                float n1 = p1[2 + dc], n2 = p2[2 - dc];
                float sup = (m >= n1 && m >= n2) ? m : 0.f;
                s1 = sup >= 0.3f;
                w1 = (sup >= 0.1f) && (sup < 0.3f);
            }
            unsigned vs = (s0 ? 1u : 0u) | (s1 ? 2u : 0u);
            unsigned vw = (w0 ? 1u : 0u) | (w1 ? 2u : 0u);
            unsigned mask = ((t >> 4) & 1) ? 0xFFFF0000u : 0x0000FFFFu;
            int sh = 2 * (t & 15);
            unsigned ws = __reduce_or_sync(mask, vs << sh);
            unsigned ww = __reduce_or_sync(mask, vw << sh);
            if ((t & 15) == 0) {
                int idx = (b * IMH + (r - 5)) * WPR + (cx >> 5);
                g_strong[idx] = ws;
                g_weak[idx]   = ww;
            }
        }

        // ---- ring shifts ----
        blp = bln;
        magp.x = magn[0]; magp.y = magn[1];
        binm2[0] = binm1[0]; binm2[1] = binm1[1];
        binm1[0] = binn[0]; binm1[1] = binn[1];
        rv = rvn;
    }
}

// ---------------------------------------------------------------------------
// K2: 16 hysteresis iterations, rows in registers (6/warp), horizontal word
// neighbors via shuffles, vertical strip-boundary rows via tiny double-
// buffered smem exchange. One barrier per iteration. Tile = 48 data rows
// (16 halo + 16 interior + 16 halo), full 1024 width; grid 64x8 = 512 blocks.
// Stale-halo front advances 1 row/iter -> interior exact after 16 iters.
// ---------------------------------------------------------------------------
__global__ void __launch_bounds__(256) canny_hyst(float* __restrict__ out)
{
    __shared__ uint32_t sm_top[2][8][32];
    __shared__ uint32_t sm_bot[2][8][32];
    __shared__ uint32_t Efin[16][32];

    const int tid  = threadIdx.x;
    const int lane = tid & 31;           // word column
    const int w    = tid >> 5;           // warp id 0..7 -> data rows 6w..6w+5
    const int by   = blockIdx.x;         // 0..63
    const int b    = blockIdx.y;
    const int r0   = by * 16;

    uint32_t e[6], wk[6];
    #pragma unroll
    for (int k = 0; k < 6; k++) {
        int gr = r0 - 16 + 6 * w + k;
        uint32_t ev = 0u, wv = 0u;
        if ((unsigned)gr < IMH) {
            int idx = (b * IMH + gr) * WPR + lane;
            ev = g_strong[idx];
            wv = g_weak[idx];
        }
        e[k] = ev; wk[k] = wv;
    }

    #pragma unroll 2
    for (int it = 0; it < 16; ++it) {
        const int p = it & 1;
        sm_top[p][w][lane] = e[0];
        sm_bot[p][w][lane] = e[5];
        __syncthreads();
        uint32_t above = (w > 0) ? sm_bot[p][w - 1][lane] : 0u;
        uint32_t below = (w < 7) ? sm_top[p][w + 1][lane] : 0u;

        uint32_t rowv[8];
        rowv[0] = above;
        #pragma unroll
        for (int k = 0; k < 6; k++) rowv[k + 1] = e[k];
        rowv[7] = below;

        uint32_t h[8];
        #pragma unroll
        for (int k = 0; k < 8; k++) {
            uint32_t m = rowv[k];
            uint32_t l  = __shfl_up_sync(0xffffffffu, m, 1);
            uint32_t rr = __shfl_down_sync(0xffffffffu, m, 1);
            if (lane == 0)  l = 0u;
            if (lane == 31) rr = 0u;
            h[k] = m | (m << 1) | (m >> 1) | (l >> 31) | (rr << 31);
        }
        #pragma unroll
        for (int k = 0; k < 6; k++)
            e[k] = e[k] | (wk[k] & (h[k] | h[k + 1] | h[k + 2]));
    }

    // publish interior rows (data rows 16..31 -> global rows r0..r0+15)
    #pragma unroll
    for (int k = 0; k < 6; k++) {
        int dr = 6 * w + k;
        if (dr >= 16 && dr < 32) Efin[dr - 16][lane] = e[k];
    }
    __syncthreads();

    float4* o = (float4*)(out + (size_t)b * IMH * IMW + (size_t)r0 * IMW);
    #pragma unroll
    for (int u = tid; u < 16 * 256; u += 256) {
        int row = u >> 8;                 // 256 float4 per image row
        int q   = u & 255;
        int colpx = q << 2;
        uint32_t word = Efin[row][colpx >> 5];
        int sh = colpx & 31;
        float4 v;
        v.x = (float)((word >> sh)       & 1u);
        v.y = (float)((word >> (sh + 1)) & 1u);
        v.z = (float)((word >> (sh + 2)) & 1u);
        v.w = (float)((word >> (sh + 3)) & 1u);
        o[(row << 8) + q] = v;
    }
}

extern "C" void kernel_launch(void* const* d_in, const int* in_sizes, int n_in,
                              void* d_out, int out_size)
{
    const float* in = (const float*)d_in[0];
    float* out = (float*)d_out;

    dim3 g1(IMH / ROWS1, NB);     // 32 x 8
    canny_front<<<g1, 512>>>(in);

    dim3 g2(64, NB);              // 64 x 8
    canny_hyst<<<g2, 256>>>(out);
}

// round 9
// speedup vs baseline: 1.0067x; 1.0067x over previous
#include <cuda_runtime.h>
#include <stdint.h>

#define IMH 1024
#define IMW 1024
#define NB  8
#define WPR 32   // 32-bit words per image row

// Bit-packed strong/weak planes (static device scratch, no allocs)
__device__ uint32_t g_strong[NB * IMH * WPR];
__device__ uint32_t g_weak[NB * IMH * WPR];

#define ROWS1 32   // output rows per canny_front block

// ---------------------------------------------------------------------------
// K1: rolling pipeline, 512 threads x 2 cols, full 1024-wide rows.
// Register windows (3 rows x 4 cols) carry vertical taps for raw/bl/mag;
// smem (depth-2 parity rings, rows of 1028 floats: data at idx 2..1025,
// zero guards at idx 1 and 1026) provides only each thread's +-1 horizontal
// neighbor scalars -> 6 LDS + 3 STS.64 per thread-iteration (was ~36 ops).
// All FP decision expressions are verbatim from the round-4 passing kernel.
// Pipeline at iter i (r = y0-3+i): store raw(r), bl(r-2), mag(r-4); sync;
// assemble windows; compute bl(r-1), mag+bin(r-3); NMS+pack row r-5.
// Hazard: slot p is re-stored in iter i+2, after iter i+1's sync, which is
// after all iter-i reads of p -> safe with one sync per iteration.
// ---------------------------------------------------------------------------
__global__ void __launch_bounds__(512) canny_front(const float* __restrict__ in)
{
    __shared__ __align__(16) float s_raw[2][1028];
    __shared__ __align__(16) float s_bl [2][1028];
    __shared__ __align__(16) float s_mag[2][1028];

    const int t  = threadIdx.x;          // 0..511
    const int b  = blockIdx.y;
    const int y0 = blockIdx.x * ROWS1;
    const float* img = in + (size_t)b * IMH * IMW;
    const int cx = 2 * t;                // owned columns cx, cx+1

    // zero guards (col -1 -> idx 1, col 1024 -> idx 1026), both parities
    if (t < 2) {
        int g = 1 + t * 1025;
        s_raw[0][g] = 0.f; s_raw[1][g] = 0.f;
        s_bl [0][g] = 0.f; s_bl [1][g] = 0.f;
        s_mag[0][g] = 0.f; s_mag[1][g] = 0.f;
    }

    // register windows: cols cx-1 .. cx+2
    float rw0[4], rw1[4], rw2[4];        // raw rows r-2, r-1, r
    float bw0[4], bw1[4], bw2[4];        // bl  rows r-4, r-3, r-2
    float mw0[4], mw1[4], mw2[4];        // mag rows r-6, r-5, r-4
    #pragma unroll
    for (int k = 0; k < 4; k++) {
        rw0[k]=rw1[k]=rw2[k]=0.f; bw0[k]=bw1[k]=bw2[k]=0.f; mw0[k]=mw1[k]=mw2[k]=0.f;
    }
    float2 blp  = make_float2(0.f, 0.f);   // bl(r-2) pending store
    float2 magp = make_float2(0.f, 0.f);   // mag(r-4) pending store
    int binm1[2] = {0,0}, binm2[2] = {0,0};

    const int r_start = y0 - 3;

    float2 rv = make_float2(0.f, 0.f);
    if ((unsigned)r_start < IMH)
        rv = ((const float2*)(img + (size_t)r_start * IMW))[t];

    #pragma unroll 2
    for (int i = 0; i < ROWS1 + 8; ++i) {
        const int r = r_start + i;
        const int p = i & 1;

        // ---- store phase (vectorized, aligned: base+2 floats = 8B) ----
        ((float2*)(s_raw[p] + 2))[t] = rv;
        ((float2*)(s_bl [p] + 2))[t] = blp;
        ((float2*)(s_mag[p] + 2))[t] = magp;
        __syncthreads();

        // prefetch raw(r+1)
        float2 rvn = make_float2(0.f, 0.f);
        if ((unsigned)(r + 1) < IMH)
            rvn = ((const float2*)(img + (size_t)(r + 1) * IMW))[t];

        // ---- window shifts + assemble new bottom rows (neighbors via smem) ----
        #pragma unroll
        for (int k = 0; k < 4; k++) { rw0[k]=rw1[k]; rw1[k]=rw2[k]; }
        rw2[0] = s_raw[p][1 + cx];
        rw2[1] = rv.x; rw2[2] = rv.y;
        rw2[3] = s_raw[p][4 + cx];

        #pragma unroll
        for (int k = 0; k < 4; k++) { bw0[k]=bw1[k]; bw1[k]=bw2[k]; }
        bw2[0] = s_bl[p][1 + cx];
        bw2[1] = blp.x; bw2[2] = blp.y;
        bw2[3] = s_bl[p][4 + cx];

        #pragma unroll
        for (int k = 0; k < 4; k++) { mw0[k]=mw1[k]; mw1[k]=mw2[k]; }
        mw2[0] = s_mag[p][1 + cx];
        mw2[1] = magp.x; mw2[2] = magp.y;
        mw2[3] = s_mag[p][4 + cx];

        // ---- blur(r-1): direct 9-tap, verbatim expression ----
        float2 bln = make_float2(0.f, 0.f);
        if (r >= y0 - 1 && (unsigned)(r - 1) < IMH) {
            bln.x = 0.0625f * rw0[0] + 0.125f * rw0[1] + 0.0625f * rw0[2]
                  + 0.125f  * rw1[0] + 0.25f  * rw1[1] + 0.125f  * rw1[2]
                  + 0.0625f * rw2[0] + 0.125f * rw2[1] + 0.0625f * rw2[2];
            bln.y = 0.0625f * rw0[1] + 0.125f * rw0[2] + 0.0625f * rw0[3]
                  + 0.125f  * rw1[1] + 0.25f  * rw1[2] + 0.125f  * rw1[3]
                  + 0.0625f * rw2[1] + 0.125f * rw2[2] + 0.0625f * rw2[3];
        }

        // ---- sobel + mag + bin at row r-3: verbatim expressions ----
        float magn[2] = {0.f, 0.f};
        int   binn[2] = {0, 0};
        if (r >= y0 + 2 && (unsigned)(r - 3) < IMH) {
            #pragma unroll
            for (int j = 0; j < 2; j++) {
                float gx = (bw0[j+2] - bw0[j]) + 2.0f * (bw1[j+2] - bw1[j]) + (bw2[j+2] - bw2[j]);
                float gy = (bw2[j] - bw0[j]) + 2.0f * (bw2[j+1] - bw0[j+1]) + (bw2[j+2] - bw0[j+2]);
                magn[j] = sqrtf(gx * gx + gy * gy);
                float ax = fabsf(gx), ay = fabsf(gy);
                bool ss = ((__float_as_uint(gx) ^ __float_as_uint(gy)) >> 31) == 0u;
                binn[j] = (ay < 0.41421356237309503f * ax) ? 0 :
                          (ay >= 2.414213562373095f  * ax) ? 2 : (ss ? 1 : 3);
            }
        }

        // ---- NMS + double threshold + bitpack at row r-5 ----
        if (i >= 8) {
            bool s0, w0, s1, w1;
            {
                float m = mw1[1];
                int bin = binm2[0];
                int dc = (bin <= 1) ? 1 : ((bin == 2) ? 0 : -1);
                const float* p1 = (bin == 0) ? mw1 : mw0;
                const float* p2 = (bin == 0) ? mw1 : mw2;
                float n1 = p1[1 + dc], n2 = p2[1 - dc];
                float sup = (m >= n1 && m >= n2) ? m : 0.f;
                s0 = sup >= 0.3f;
                w0 = (sup >= 0.1f) && (sup < 0.3f);
            }
            {
                float m = mw1[2];
                int bin = binm2[1];
                int dc = (bin <= 1) ? 1 : ((bin == 2) ? 0 : -1);
                const float* p1 = (bin == 0) ? mw1 : mw0;
                const float* p2 = (bin == 0) ? mw1 : mw2;
                float n1 = p1[2 + dc], n2 = p2[2 - dc];
                float sup = (m >= n1 && m >= n2) ? m : 0.f;
                s1 = sup >= 0.3f;
                w1 = (sup >= 0.1f) && (sup < 0.3f);
            }
            unsigned vs = (s0 ? 1u : 0u) | (s1 ? 2u : 0u);
            unsigned vw = (w0 ? 1u : 0u) | (w1 ? 2u : 0u);
            unsigned mask = ((t >> 4) & 1) ? 0xFFFF0000u : 0x0000FFFFu;
            int sh = 2 * (t & 15);
            unsigned ws = __reduce_or_sync(mask, vs << sh);
            unsigned ww = __reduce_or_sync(mask, vw << sh);
            if ((t & 15) == 0) {
                int idx = (b * IMH + (r - 5)) * WPR + (cx >> 5);
                g_strong[idx] = ws;
                g_weak[idx]   = ww;
            }
        }

        // ---- ring shifts ----
        blp = bln;
        magp.x = magn[0]; magp.y = magn[1];
        binm2[0] = binm1[0]; binm2[1] = binm1[1];
        binm1[0] = binn[0]; binm1[1] = binn[1];
        rv = rvn;
    }
}

// ---------------------------------------------------------------------------
// K2: 16 hysteresis iterations, rows in registers (6/warp), horizontal word
// neighbors via shuffles, vertical strip-boundary rows via tiny double-
// buffered smem exchange. One barrier per iteration. Tile = 48 data rows
// (16 halo + 16 interior + 16 halo), full 1024 width; grid 64x8 = 512 blocks.
// Stale-halo front advances 1 row/iter -> interior exact after 16 iters.
// ---------------------------------------------------------------------------
__global__ void __launch_bounds__(256) canny_hyst(float* __restrict__ out)
{
    __shared__ uint32_t sm_top[2][8][32];
    __shared__ uint32_t sm_bot[2][8][32];
    __shared__ uint32_t Efin[16][32];

    const int tid  = threadIdx.x;
    const int lane = tid & 31;           // word column
    const int w    = tid >> 5;           // warp id 0..7 -> data rows 6w..6w+5
    const int by   = blockIdx.x;         // 0..63
    const int b    = blockIdx.y;
    const int r0   = by * 16;

    uint32_t e[6], wk[6];
    #pragma unroll
    for (int k = 0; k < 6; k++) {
        int gr = r0 - 16 + 6 * w + k;
        uint32_t ev = 0u, wv = 0u;
        if ((unsigned)gr < IMH) {
            int idx = (b * IMH + gr) * WPR + lane;
            ev = g_strong[idx];
            wv = g_weak[idx];
        }
        e[k] = ev; wk[k] = wv;
    }

    #pragma unroll 2
    for (int it = 0; it < 16; ++it) {
        const int p = it & 1;
        sm_top[p][w][lane] = e[0];
        sm_bot[p][w][lane] = e[5];
        __syncthreads();
        uint32_t above = (w > 0) ? sm_bot[p][w - 1][lane] : 0u;
        uint32_t below = (w < 7) ? sm_top[p][w + 1][lane] : 0u;

        uint32_t rowv[8];
        rowv[0] = above;
        #pragma unroll
        for (int k = 0; k < 6; k++) rowv[k + 1] = e[k];
        rowv[7] = below;

        uint32_t h[8];
        #pragma unroll
        for (int k = 0; k < 8; k++) {
            uint32_t m = rowv[k];
            uint32_t l  = __shfl_up_sync(0xffffffffu, m, 1);
            uint32_t rr = __shfl_down_sync(0xffffffffu, m, 1);
            if (lane == 0)  l = 0u;
            if (lane == 31) rr = 0u;
            h[k] = m | (m << 1) | (m >> 1) | (l >> 31) | (rr << 31);
        }
        #pragma unroll
        for (int k = 0; k < 6; k++)
            e[k] = e[k] | (wk[k] & (h[k] | h[k + 1] | h[k + 2]));
    }

    // publish interior rows (data rows 16..31 -> global rows r0..r0+15)
    #pragma unroll
    for (int k = 0; k < 6; k++) {
        int dr = 6 * w + k;
        if (dr >= 16 && dr < 32) Efin[dr - 16][lane] = e[k];
    }
    __syncthreads();

    float4* o = (float4*)(out + (size_t)b * IMH * IMW + (size_t)r0 * IMW);
    #pragma unroll
    for (int u = tid; u < 16 * 256; u += 256) {
        int row = u >> 8;                 // 256 float4 per image row
        int q   = u & 255;
        int colpx = q << 2;
        uint32_t word = Efin[row][colpx >> 5];
        int sh = colpx & 31;
        float4 v;
        v.x = (float)((word >> sh)       & 1u);
        v.y = (float)((word >> (sh + 1)) & 1u);
        v.z = (float)((word >> (sh + 2)) & 1u);
        v.w = (float)((word >> (sh + 3)) & 1u);
        o[(row << 8) + q] = v;
    }
}

extern "C" void kernel_launch(void* const* d_in, const int* in_sizes, int n_in,
                              void* d_out, int out_size)
{
    const float* in = (const float*)d_in[0];
    float* out = (float*)d_out;

    dim3 g1(IMH / ROWS1, NB);     // 32 x 8
    canny_front<<<g1, 512>>>(in);

    dim3 g2(64, NB);              // 64 x 8
    canny_hyst<<<g2, 256>>>(out);
}